// round 1
// baseline (speedup 1.0000x reference)
#include <cuda_runtime.h>
#include <math_constants.h>

// WorkingMemory: B=1024 rows. Per row:
//   raw[j] = sum_k a1[k] + sum_k (a0[k]-a1[k]) * bit_{9-k}(j),  j in [0,1024)
//   y2 = LSE_{j>=512}(raw) - log(512)
//   attn[i] = logaddexp(raw[i], y2), i < 512
//   e_i = exp(attn_i - mx), S = sum e, ssq = sum e^2, w_i = e_i*(S - e_i)
//   r{0,1}[b,c] = 2*mx + log( sum_i w_i * exp(m{0,1}[b,i,c]) + exp(v{0,1}[b,c]) * ssq )
// out shape (2, B, C).

#define BB 1024
#define AA 512
#define CC 64
#define DD 10
#define NTH 512

__device__ __forceinline__ float blockReduceMax(float v, float* sbuf) {
    #pragma unroll
    for (int o = 16; o; o >>= 1) v = fmaxf(v, __shfl_xor_sync(0xffffffffu, v, o));
    int warp = threadIdx.x >> 5;
    if ((threadIdx.x & 31) == 0) sbuf[warp] = v;
    __syncthreads();
    if (threadIdx.x < 32) {
        float x = (threadIdx.x < (NTH / 32)) ? sbuf[threadIdx.x] : -CUDART_INF_F;
        #pragma unroll
        for (int o = 8; o; o >>= 1) x = fmaxf(x, __shfl_xor_sync(0xffffffffu, x, o));
        if (threadIdx.x == 0) sbuf[0] = x;
    }
    __syncthreads();
    float r = sbuf[0];
    __syncthreads();
    return r;
}

__device__ __forceinline__ float blockReduceSum(float v, float* sbuf) {
    #pragma unroll
    for (int o = 16; o; o >>= 1) v += __shfl_xor_sync(0xffffffffu, v, o);
    int warp = threadIdx.x >> 5;
    if ((threadIdx.x & 31) == 0) sbuf[warp] = v;
    __syncthreads();
    if (threadIdx.x < 32) {
        float x = (threadIdx.x < (NTH / 32)) ? sbuf[threadIdx.x] : 0.0f;
        #pragma unroll
        for (int o = 8; o; o >>= 1) x += __shfl_xor_sync(0xffffffffu, x, o);
        if (threadIdx.x == 0) sbuf[0] = x;
    }
    __syncthreads();
    float r = sbuf[0];
    __syncthreads();
    return r;
}

__global__ __launch_bounds__(NTH)
void wm_kernel(const float* __restrict__ m0, const float* __restrict__ m1,
               const float* __restrict__ a0, const float* __restrict__ a1,
               const float* __restrict__ v0, const float* __restrict__ v1,
               float* __restrict__ out)
{
    __shared__ float sred[32];
    __shared__ float sw[AA];
    __shared__ float racc[2][CC][33];   // padded: bank-conflict-free column sums

    const int b   = blockIdx.x;
    const int tid = threadIdx.x;

    // ---------------- phase 1: attn weights (tiny) ----------------
    float base = 0.0f;
    float diff[DD];
    {
        const float* pa0 = a0 + b * DD;
        const float* pa1 = a1 + b * DD;
        #pragma unroll
        for (int k = 0; k < DD; k++) {
            float x1 = pa1[k];
            base += x1;
            diff[k] = pa0[k] - x1;
        }
    }
    // raw for j = tid (low half) and j = tid + 512 (high half); bits MSB-first
    const int jlo = tid;
    const int jhi = tid + AA;
    float rlo = base, rhi = base;
    #pragma unroll
    for (int k = 0; k < DD; k++) {
        if ((jlo >> (9 - k)) & 1) rlo += diff[k];
        if ((jhi >> (9 - k)) & 1) rhi += diff[k];
    }

    float maxh = blockReduceMax(rhi, sred);
    float sumh = blockReduceSum(__expf(rhi - maxh), sred);
    const float LOG512 = 6.238324625039508f;     // log(NADDR - A)
    float y2 = maxh + __logf(sumh) - LOG512;

    // attn = logaddexp(rlo, y2)
    float mab  = fmaxf(rlo, y2);
    float attn = mab + log1pf(__expf(-fabsf(rlo - y2)));

    float mx  = blockReduceMax(attn, sred);
    float e   = __expf(attn - mx);
    float S   = blockReduceSum(e, sred);
    float ssq = blockReduceSum(e * e, sred);

    sw[tid] = e * (S - e);                        // exp(attn_i + nattn_i - 2mx)
    __syncthreads();

    // ---------------- phase 2: stream m0/m1 slab (memory-bound) ----------------
    const int c4 = tid & 15;        // which float4 in the 64-float row
    const int ig = tid >> 4;        // i-group, 0..31

    const float4* p0 = (const float4*)m0 + (size_t)b * (AA * CC / 4);
    const float4* p1 = (const float4*)m1 + (size_t)b * (AA * CC / 4);

    float4 acc0 = make_float4(0.f, 0.f, 0.f, 0.f);
    float4 acc1 = make_float4(0.f, 0.f, 0.f, 0.f);

    #pragma unroll 4
    for (int i = ig; i < AA; i += 32) {
        float  w  = sw[i];
        float4 x0 = p0[i * 16 + c4];
        float4 x1 = p1[i * 16 + c4];
        acc0.x = fmaf(w, __expf(x0.x), acc0.x);
        acc0.y = fmaf(w, __expf(x0.y), acc0.y);
        acc0.z = fmaf(w, __expf(x0.z), acc0.z);
        acc0.w = fmaf(w, __expf(x0.w), acc0.w);
        acc1.x = fmaf(w, __expf(x1.x), acc1.x);
        acc1.y = fmaf(w, __expf(x1.y), acc1.y);
        acc1.z = fmaf(w, __expf(x1.z), acc1.z);
        acc1.w = fmaf(w, __expf(x1.w), acc1.w);
    }

    const int cb = c4 * 4;
    racc[0][cb + 0][ig] = acc0.x;
    racc[0][cb + 1][ig] = acc0.y;
    racc[0][cb + 2][ig] = acc0.z;
    racc[0][cb + 3][ig] = acc0.w;
    racc[1][cb + 0][ig] = acc1.x;
    racc[1][cb + 1][ig] = acc1.y;
    racc[1][cb + 2][ig] = acc1.z;
    racc[1][cb + 3][ig] = acc1.w;
    __syncthreads();

    // ---------------- finalize: 128 outputs per row ----------------
    if (tid < 2 * CC) {
        const int m = tid >> 6;     // matrix 0/1
        const int c = tid & 63;
        float s = 0.0f;
        #pragma unroll
        for (int g = 0; g < 32; g++) s += racc[m][c][g];
        const float* vv = m ? v1 : v0;
        float r = 2.0f * mx + __logf(s + __expf(vv[b * CC + c]) * ssq);
        out[(size_t)m * BB * CC + (size_t)b * CC + c] = r;
    }
}

extern "C" void kernel_launch(void* const* d_in, const int* in_sizes, int n_in,
                              void* d_out, int out_size) {
    const float* m0 = (const float*)d_in[0];
    const float* m1 = (const float*)d_in[1];
    const float* a0 = (const float*)d_in[2];
    const float* a1 = (const float*)d_in[3];
    const float* v0 = (const float*)d_in[4];
    const float* v1 = (const float*)d_in[5];
    // d_in[6], d_in[7] (b_0, b_1) are synthesized in-kernel from bit patterns.
    float* out = (float*)d_out;
    wm_kernel<<<BB, NTH>>>(m0, m1, a0, a1, v0, v1, out);
}

// round 2
// speedup vs baseline: 1.0110x; 1.0110x over previous
#include <cuda_runtime.h>
#include <math_constants.h>

// WorkingMemory, restructured algebraically:
//   raw[j] = sum_k a1[k] + sum_k (a0[k]-a1[k]) * bit_{9-k}(j)
//   y2 = LSE_{j>=512}(raw) - log(512)
//   attn[i] = logaddexp(raw[i], y2)
//   e_i = exp(attn_i - mx); S = sum e; ssq = sum e^2; w_i = e_i*(S - e_i)
//   r{0,1}[b,c] = 2*mx + log( sum_i w_i * exp(m{0,1}[b,i,c]) + exp(v{0,1}[b,c]) * ssq )
// out shape (2, B, C).
//
// R2: 256-thread CTAs so all 1024 CTAs are resident in ONE wave
// (7 CTAs/SM x 148 = 1036 slots) -> no wave quantization.

#define BB 1024
#define AA 512
#define CC 64
#define DD 10
#define NTH 256
#define NWARP (NTH / 32)

__device__ __forceinline__ float blockReduceMax(float v, float* sbuf) {
    #pragma unroll
    for (int o = 16; o; o >>= 1) v = fmaxf(v, __shfl_xor_sync(0xffffffffu, v, o));
    int warp = threadIdx.x >> 5;
    if ((threadIdx.x & 31) == 0) sbuf[warp] = v;
    __syncthreads();
    if (threadIdx.x < 32) {
        float x = (threadIdx.x < NWARP) ? sbuf[threadIdx.x] : -CUDART_INF_F;
        #pragma unroll
        for (int o = 4; o; o >>= 1) x = fmaxf(x, __shfl_xor_sync(0xffffffffu, x, o));
        if (threadIdx.x == 0) sbuf[0] = x;
    }
    __syncthreads();
    float r = sbuf[0];
    __syncthreads();
    return r;
}

__device__ __forceinline__ float blockReduceSum(float v, float* sbuf) {
    #pragma unroll
    for (int o = 16; o; o >>= 1) v += __shfl_xor_sync(0xffffffffu, v, o);
    int warp = threadIdx.x >> 5;
    if ((threadIdx.x & 31) == 0) sbuf[warp] = v;
    __syncthreads();
    if (threadIdx.x < 32) {
        float x = (threadIdx.x < NWARP) ? sbuf[threadIdx.x] : 0.0f;
        #pragma unroll
        for (int o = 4; o; o >>= 1) x += __shfl_xor_sync(0xffffffffu, x, o);
        if (threadIdx.x == 0) sbuf[0] = x;
    }
    __syncthreads();
    float r = sbuf[0];
    __syncthreads();
    return r;
}

__global__ __launch_bounds__(NTH, 7)
void wm_kernel(const float* __restrict__ m0, const float* __restrict__ m1,
               const float* __restrict__ a0, const float* __restrict__ a1,
               const float* __restrict__ v0, const float* __restrict__ v1,
               float* __restrict__ out)
{
    __shared__ float sred[32];
    __shared__ float sw[AA];
    __shared__ float racc[2][CC][17];   // [matrix][channel][i-group], padded

    const int b   = blockIdx.x;
    const int tid = threadIdx.x;

    // ---------------- phase 1: attn weights (tiny) ----------------
    float base = 0.0f;
    float diff[DD];
    {
        const float* pa0 = a0 + b * DD;
        const float* pa1 = a1 + b * DD;
        #pragma unroll
        for (int k = 0; k < DD; k++) {
            float x1 = pa1[k];
            base += x1;
            diff[k] = pa0[k] - x1;
        }
    }
    // each thread handles 2 low-half and 2 high-half addresses
    const int j0 = tid;          // low
    const int j1 = tid + 256;    // low
    const int j2 = tid + 512;    // high
    const int j3 = tid + 768;    // high
    float r0 = base, r1 = base, r2 = base, r3 = base;
    #pragma unroll
    for (int k = 0; k < DD; k++) {
        int sh = 9 - k;
        if ((j0 >> sh) & 1) r0 += diff[k];
        if ((j1 >> sh) & 1) r1 += diff[k];
        if ((j2 >> sh) & 1) r2 += diff[k];
        if ((j3 >> sh) & 1) r3 += diff[k];
    }

    float maxh = blockReduceMax(fmaxf(r2, r3), sred);
    float sumh = blockReduceSum(__expf(r2 - maxh) + __expf(r3 - maxh), sred);
    const float LOG512 = 6.238324625039508f;     // log(NADDR - A)
    float y2 = maxh + __logf(sumh) - LOG512;

    // attn = logaddexp(raw_low, y2) for the two low-half lanes
    float ma0 = fmaxf(r0, y2);
    float at0 = ma0 + log1pf(__expf(-fabsf(r0 - y2)));
    float ma1 = fmaxf(r1, y2);
    float at1 = ma1 + log1pf(__expf(-fabsf(r1 - y2)));

    float mx  = blockReduceMax(fmaxf(at0, at1), sred);
    float e0  = __expf(at0 - mx);
    float e1  = __expf(at1 - mx);
    float S   = blockReduceSum(e0 + e1, sred);
    float ssq = blockReduceSum(e0 * e0 + e1 * e1, sred);

    sw[j0] = e0 * (S - e0);      // exp(attn_i + nattn_i - 2mx)
    sw[j1] = e1 * (S - e1);
    __syncthreads();

    // ---------------- phase 2: stream m0/m1 slab (memory-bound) ----------------
    const int c4 = tid & 15;     // which float4 within the 64-float channel row
    const int ig = tid >> 4;     // i-group, 0..15

    const float4* p0 = (const float4*)m0 + (size_t)b * (AA * CC / 4);
    const float4* p1 = (const float4*)m1 + (size_t)b * (AA * CC / 4);

    float4 acc0 = make_float4(0.f, 0.f, 0.f, 0.f);
    float4 acc1 = make_float4(0.f, 0.f, 0.f, 0.f);

    #pragma unroll 4
    for (int i = ig; i < AA; i += 16) {
        float  w  = sw[i];
        float4 x0 = p0[i * 16 + c4];
        float4 x1 = p1[i * 16 + c4];
        acc0.x = fmaf(w, __expf(x0.x), acc0.x);
        acc0.y = fmaf(w, __expf(x0.y), acc0.y);
        acc0.z = fmaf(w, __expf(x0.z), acc0.z);
        acc0.w = fmaf(w, __expf(x0.w), acc0.w);
        acc1.x = fmaf(w, __expf(x1.x), acc1.x);
        acc1.y = fmaf(w, __expf(x1.y), acc1.y);
        acc1.z = fmaf(w, __expf(x1.z), acc1.z);
        acc1.w = fmaf(w, __expf(x1.w), acc1.w);
    }

    const int cb = c4 * 4;
    racc[0][cb + 0][ig] = acc0.x;
    racc[0][cb + 1][ig] = acc0.y;
    racc[0][cb + 2][ig] = acc0.z;
    racc[0][cb + 3][ig] = acc0.w;
    racc[1][cb + 0][ig] = acc1.x;
    racc[1][cb + 1][ig] = acc1.y;
    racc[1][cb + 2][ig] = acc1.z;
    racc[1][cb + 3][ig] = acc1.w;
    __syncthreads();

    // ---------------- finalize: 128 outputs per row ----------------
    if (tid < 2 * CC) {
        const int m = tid >> 6;     // matrix 0/1
        const int c = tid & 63;
        float s = 0.0f;
        #pragma unroll
        for (int g = 0; g < 16; g++) s += racc[m][c][g];
        const float* vv = m ? v1 : v0;
        float r = 2.0f * mx + __logf(s + __expf(vv[b * CC + c]) * ssq);
        out[(size_t)m * BB * CC + (size_t)b * CC + c] = r;
    }
}

extern "C" void kernel_launch(void* const* d_in, const int* in_sizes, int n_in,
                              void* d_out, int out_size) {
    const float* m0 = (const float*)d_in[0];
    const float* m1 = (const float*)d_in[1];
    const float* a0 = (const float*)d_in[2];
    const float* a1 = (const float*)d_in[3];
    const float* v0 = (const float*)d_in[4];
    const float* v1 = (const float*)d_in[5];
    // d_in[6], d_in[7] (b_0, b_1) are synthesized in-kernel from bit patterns.
    float* out = (float*)d_out;
    wm_kernel<<<BB, NTH>>>(m0, m1, a0, a1, v0, v1, out);
}